// round 13
// baseline (speedup 1.0000x reference)
#include <cuda_runtime.h>
#include <math_constants.h>

#define FULLMASK 0xffffffffu
typedef unsigned long long ull;

static constexpr int Bc = 4;
static constexpr int Nc = 4096;
static constexpr int S1 = 2048;
static constexpr int S2 = 512;
static constexpr int Kc = 64;

// ---------------- scratch (device globals; no allocation allowed) ----------------
__device__ float g_qpos1[Bc * S1 * 3];
__device__ float g_qpos2[Bc * S2 * 3];
__device__ int   g_nidx2[Bc * S2 * Kc];
__device__ int   g_cnt2[Bc * S2];
__device__ float g_feat1[Bc * S1 * 64];
__device__ float g_bufA[Bc * S2 * Kc * 64];
__device__ float g_bufB[Bc * S2 * Kc * 64];
// FPS point caches (x,y,z,|p|^2) — global instead of smem so the mega kernel
// keeps a small uniform smem footprint; winner lookup is an L1-hit LDG.128.
__device__ __align__(16) float4 g_spts1[Bc * Nc];
__device__ __align__(16) float4 g_spts2[Bc * S1];
// progress counters (reset每 run by reset_kernel — stale across graph replays!)
__device__ int g_prog1[Bc];
__device__ int g_prog2[Bc];

// ---------------- packed f32x2 helpers ----------------
__device__ __forceinline__ ull pk2(float lo, float hi) {
    ull r; asm("mov.b64 %0, {%1, %2};" : "=l"(r) : "f"(lo), "f"(hi)); return r;
}
__device__ __forceinline__ void upk2(float& lo, float& hi, ull v) {
    asm("mov.b64 {%0, %1}, %2;" : "=f"(lo), "=f"(hi) : "l"(v));
}
__device__ __forceinline__ ull fma2_(ull a, ull b, ull c) {
    ull d; asm("fma.rn.f32x2 %0, %1, %2, %3;" : "=l"(d) : "l"(a), "l"(b), "l"(c)); return d;
}
__device__ __forceinline__ ull add2_(ull a, ull b) {
    ull d; asm("add.rn.f32x2 %0, %1, %2;" : "=l"(d) : "l"(a), "l"(b)); return d;
}

// ---------------- FPS body: __syncthreads + REDUX (proven R8/R11 core) ----------------
// Publishes progress[pub] every (pubmask+1) steps with threadfence so consumer
// warps in other blocks can start per-query work while FPS is still running.
// NOTE: volatile spin-sync INSIDE fps regressed +1.27ms (R9/R10). Do not retry.
template <int NPT, int NTH>
__device__ __forceinline__ void fps_body(const float* __restrict__ P, int pstride,
                                         int n, int nsamp, float* __restrict__ qpos,
                                         float4* __restrict__ spts,
                                         int* prog, int pubmask)
{
    constexpr int NW = NTH / 32;
    __shared__ ull skey[2][NW];
    const int t = threadIdx.x, lane = t & 31, warp = t >> 5;

    ull px2[NPT / 2], py2[NPT / 2], pz2[NPT / 2], nr2[NPT / 2];
    float md[NPT];
    const int i0 = t * NPT;
#pragma unroll
    for (int k2 = 0; k2 < NPT / 2; k2++) {
        const float* pA = P + (size_t)(i0 + 2 * k2) * pstride;
        const float* pB = pA + pstride;
        float ax = pA[0], ay = pA[1], az = pA[2];
        float bx = pB[0], by = pB[1], bz = pB[2];
        float na = __fmaf_rn(az, az, __fmaf_rn(ay, ay, ax * ax));
        float nb = __fmaf_rn(bz, bz, __fmaf_rn(by, by, bx * bx));
        px2[k2] = pk2(ax, bx); py2[k2] = pk2(ay, by);
        pz2[k2] = pk2(az, bz); nr2[k2] = pk2(na, nb);
        spts[i0 + 2 * k2]     = make_float4(ax, ay, az, na);
        spts[i0 + 2 * k2 + 1] = make_float4(bx, by, bz, nb);
        md[2 * k2] = CUDART_INF_F; md[2 * k2 + 1] = CUDART_INF_F;
    }
    __syncthreads();
    float4 c = spts[0];
    if (t == 0) { qpos[0] = c.x; qpos[1] = c.y; qpos[2] = c.z; }

    for (int step = 1; step < nsamp; step++) {
        const ull KX = pk2(-2.f * c.x, -2.f * c.x);
        const ull KY = pk2(-2.f * c.y, -2.f * c.y);
        const ull KZ = pk2(-2.f * c.z, -2.f * c.z);
        const ull CC = pk2(c.w, c.w);
        float bm = -CUDART_INF_F; int bi = 0;
#pragma unroll
        for (int k2 = 0; k2 < NPT / 2; k2++) {
            ull e = fma2_(pz2[k2], KZ, nr2[k2]);
            e = fma2_(py2[k2], KY, e);
            e = fma2_(px2[k2], KX, e);
            e = add2_(e, CC);
            float e0, e1; upk2(e0, e1, e);
            float m0 = fminf(md[2 * k2], e0);     md[2 * k2] = m0;
            float m1 = fminf(md[2 * k2 + 1], e1); md[2 * k2 + 1] = m1;
            if (m0 > bm) { bm = m0; bi = i0 + 2 * k2; }
            if (m1 > bm) { bm = m1; bi = i0 + 2 * k2 + 1; }
        }
        bm = fmaxf(bm, 0.0f);   // keep unsigned bit order valid
        unsigned hbits = __float_as_uint(bm);
        unsigned hmax = __reduce_max_sync(FULLMASK, hbits);
        unsigned locand = (hbits == hmax) ? (unsigned)(n - 1 - bi) : 0u;
        unsigned lomax = __reduce_max_sync(FULLMASK, locand);
        if (lane == 0) skey[step & 1][warp] = ((ull)hmax << 32) | lomax;
        __syncthreads();
        ull best = skey[step & 1][0];
#pragma unroll
        for (int w = 1; w < NW; w++) {
            ull o = skey[step & 1][w];
            if (o > best) best = o;
        }
        int wi = n - 1 - (int)(unsigned)(best & 0xffffffffull);
        c = spts[wi];
        if (t == 0) {
            float* o = qpos + (size_t)step * 3;
            o[0] = c.x; o[1] = c.y; o[2] = c.z;
            if ((step & pubmask) == 0 || step == nsamp - 1) {
                __threadfence();
                *(volatile int*)prog = step + 1;
            }
        }
    }
}

// ---------------- consumer wait: poll + acquire fence ----------------
__device__ __forceinline__ void wait_prog(const int* p, int need)
{
    while (*(volatile const int*)p < need) __nanosleep(256);
    __threadfence();
}

// ---------------- mega kernel: fps1+fps2 || per-query stage1 pipeline || ball2 ----------------
static constexpr int NB_FPS = Bc;                  // 4
static constexpr int NB_S1  = (Bc * S1) / 8;       // 1024 (8 warps/block, 1 query/warp)
static constexpr int NB_B2  = (Bc * S2) / 8;       // 256
static constexpr int NB_MEGA = NB_FPS + NB_S1 + NB_B2;   // 1284

__global__ void __launch_bounds__(256, 2)
mega_kernel(const float* __restrict__ x,
            const float* __restrict__ W1, const float* __restrict__ B1,
            const float* __restrict__ W2, const float* __restrict__ B2,
            const float* __restrict__ WC, const float* __restrict__ BC)
{
    const int bid = blockIdx.x;

    // ---- role 1: FPS producer (one CTA per batch; fps1 then fps2) ----
    if (bid < NB_FPS) {
        const int b = bid;
        fps_body<16, 256>(x + (size_t)b * Nc * 6, 6, Nc, S1,
                          g_qpos1 + (size_t)b * S1 * 3, g_spts1 + (size_t)b * Nc,
                          &g_prog1[b], 15);
        __syncthreads();   // all threads must see t0's final qpos1 writes before fps2 loads
        fps_body<8, 256>(g_qpos1 + (size_t)b * S1 * 3, 3, S1, S2,
                         g_qpos2 + (size_t)b * S2 * 3, g_spts2 + (size_t)b * S1,
                         &g_prog2[b], 7);
        return;
    }

    // ---- role 2: stage-1 per-query pipeline: poll -> ball -> MLP -> maxpool ----
    if (bid < NB_FPS + NB_S1) {
        __shared__ __align__(16) float sW1[6 * 32];
        __shared__ float sB1[32];
        __shared__ __align__(16) float sW2[32 * 32];
        __shared__ float sB2[32];
        __shared__ __align__(16) float sWC[32 * 64];
        __shared__ float sBC[64];
        __shared__ int   snidx[8][Kc];
        __shared__ float sOut[8][64];
        for (int i = threadIdx.x; i < 6 * 32; i += 256) sW1[i] = W1[i];
        if (threadIdx.x < 32) { sB1[threadIdx.x] = B1[threadIdx.x]; sB2[threadIdx.x] = B2[threadIdx.x]; }
        for (int i = threadIdx.x; i < 32 * 32; i += 256) sW2[i] = W2[i];
        for (int i = threadIdx.x; i < 32 * 64; i += 256) sWC[i] = WC[i];
        if (threadIdx.x < 64) sBC[threadIdx.x] = BC[threadIdx.x];
        __syncthreads();

        const int lane = threadIdx.x & 31;
        const int wl = threadIdx.x >> 5;
        // round-robin batch mapping so consumer residency order tracks all 4
        // parallel fps CTAs' production frontier
        const int tq = (bid - NB_FPS) * 8 + wl;       // 0..8191
        const int b = tq & 3;
        const int s = tq >> 2;                        // 0..2047
        const int q = (b << 11) | s;

        wait_prog(&g_prog1[b], s + 1);

        const float* qq = g_qpos1 + (size_t)q * 3;
        const float qx = qq[0], qy = qq[1], qz = qq[2];

        // ball query (first 64 in-range by ascending index) — idx stays in smem
        const float* P = x + (size_t)b * Nc * 6;
        int cnt = 0;
        for (int base = 0; base < Nc && cnt < Kc; base += 32) {
            int i = base + lane;
            const float* p = P + (size_t)i * 6;
            float dx = p[0] - qx, dy = p[1] - qy, dz = p[2] - qz;
            float d = __fmaf_rn(dz, dz, __fmaf_rn(dy, dy, dx * dx));
            bool in = (d <= 0.25f);
            unsigned m = __ballot_sync(FULLMASK, in);
            int pre = __popc(m & ((1u << lane) - 1u));
            int slot = cnt + pre;
            if (in && slot < Kc) snidx[wl][slot] = i;
            cnt += __popc(m);
        }
        if (cnt > Kc) cnt = Kc;
        for (int j = cnt + lane; j < Kc; j += 32) snidx[wl][j] = 0;
        __syncwarp();

        // fused gather -> 6->32 -> 32->32 -> 32->64 -> masked maxpool
#pragma unroll 1
        for (int r = 0; r < 2; r++) {
            int j = r * 32 + lane;
            int idx = snidx[wl][j];
            const float* rp = P + (size_t)idx * 6;
            float h0[6] = { rp[3], rp[4], rp[5], rp[0] - qx, rp[1] - qy, rp[2] - qz };
            float h1[32];
#pragma unroll 1
            for (int cg = 0; cg < 4; cg++) {
                ull a01 = pk2(sB1[cg * 8 + 0], sB1[cg * 8 + 1]);
                ull a23 = pk2(sB1[cg * 8 + 2], sB1[cg * 8 + 3]);
                ull a45 = pk2(sB1[cg * 8 + 4], sB1[cg * 8 + 5]);
                ull a67 = pk2(sB1[cg * 8 + 6], sB1[cg * 8 + 7]);
#pragma unroll
                for (int k = 0; k < 6; k++) {
                    float4 w0 = *reinterpret_cast<const float4*>(&sW1[k * 32 + cg * 8]);
                    float4 w1 = *reinterpret_cast<const float4*>(&sW1[k * 32 + cg * 8 + 4]);
                    ull hh = pk2(h0[k], h0[k]);
                    a01 = fma2_(hh, pk2(w0.x, w0.y), a01);
                    a23 = fma2_(hh, pk2(w0.z, w0.w), a23);
                    a45 = fma2_(hh, pk2(w1.x, w1.y), a45);
                    a67 = fma2_(hh, pk2(w1.z, w1.w), a67);
                }
                float v0,v1,v2,v3,v4,v5,v6,v7;
                upk2(v0, v1, a01); upk2(v2, v3, a23);
                upk2(v4, v5, a45); upk2(v6, v7, a67);
                h1[cg*8+0]=fmaxf(v0,0.f); h1[cg*8+1]=fmaxf(v1,0.f);
                h1[cg*8+2]=fmaxf(v2,0.f); h1[cg*8+3]=fmaxf(v3,0.f);
                h1[cg*8+4]=fmaxf(v4,0.f); h1[cg*8+5]=fmaxf(v5,0.f);
                h1[cg*8+6]=fmaxf(v6,0.f); h1[cg*8+7]=fmaxf(v7,0.f);
            }
            float h2[32];
#pragma unroll 1
            for (int cg = 0; cg < 4; cg++) {
                ull a01 = pk2(sB2[cg * 8 + 0], sB2[cg * 8 + 1]);
                ull a23 = pk2(sB2[cg * 8 + 2], sB2[cg * 8 + 3]);
                ull a45 = pk2(sB2[cg * 8 + 4], sB2[cg * 8 + 5]);
                ull a67 = pk2(sB2[cg * 8 + 6], sB2[cg * 8 + 7]);
#pragma unroll
                for (int k = 0; k < 32; k++) {
                    float4 w0 = *reinterpret_cast<const float4*>(&sW2[k * 32 + cg * 8]);
                    float4 w1 = *reinterpret_cast<const float4*>(&sW2[k * 32 + cg * 8 + 4]);
                    ull hh = pk2(h1[k], h1[k]);
                    a01 = fma2_(hh, pk2(w0.x, w0.y), a01);
                    a23 = fma2_(hh, pk2(w0.z, w0.w), a23);
                    a45 = fma2_(hh, pk2(w1.x, w1.y), a45);
                    a67 = fma2_(hh, pk2(w1.z, w1.w), a67);
                }
                float v0,v1,v2,v3,v4,v5,v6,v7;
                upk2(v0, v1, a01); upk2(v2, v3, a23);
                upk2(v4, v5, a45); upk2(v6, v7, a67);
                h2[cg*8+0]=fmaxf(v0,0.f); h2[cg*8+1]=fmaxf(v1,0.f);
                h2[cg*8+2]=fmaxf(v2,0.f); h2[cg*8+3]=fmaxf(v3,0.f);
                h2[cg*8+4]=fmaxf(v4,0.f); h2[cg*8+5]=fmaxf(v5,0.f);
                h2[cg*8+6]=fmaxf(v6,0.f); h2[cg*8+7]=fmaxf(v7,0.f);
            }
            bool valid = (j < cnt);
#pragma unroll 1
            for (int cg = 0; cg < 8; cg++) {
                ull a01 = pk2(sBC[cg * 8 + 0], sBC[cg * 8 + 1]);
                ull a23 = pk2(sBC[cg * 8 + 2], sBC[cg * 8 + 3]);
                ull a45 = pk2(sBC[cg * 8 + 4], sBC[cg * 8 + 5]);
                ull a67 = pk2(sBC[cg * 8 + 6], sBC[cg * 8 + 7]);
#pragma unroll
                for (int k = 0; k < 32; k++) {
                    float4 w0 = *reinterpret_cast<const float4*>(&sWC[k * 64 + cg * 8]);
                    float4 w1 = *reinterpret_cast<const float4*>(&sWC[k * 64 + cg * 8 + 4]);
                    ull hh = pk2(h2[k], h2[k]);
                    a01 = fma2_(hh, pk2(w0.x, w0.y), a01);
                    a23 = fma2_(hh, pk2(w0.z, w0.w), a23);
                    a45 = fma2_(hh, pk2(w1.x, w1.y), a45);
                    a67 = fma2_(hh, pk2(w1.z, w1.w), a67);
                }
                float v[8];
                upk2(v[0], v[1], a01); upk2(v[2], v[3], a23);
                upk2(v[4], v[5], a45); upk2(v[6], v[7], a67);
#pragma unroll
                for (int u = 0; u < 8; u++) {
                    float vv = valid ? fmaxf(v[u], 0.f) : -CUDART_INF_F;
#pragma unroll
                    for (int off = 16; off; off >>= 1)
                        vv = fmaxf(vv, __shfl_down_sync(FULLMASK, vv, off));
                    v[u] = vv;
                }
                if (lane == 0) {
                    if (r == 0) {
#pragma unroll
                        for (int u = 0; u < 8; u++) sOut[wl][cg * 8 + u] = v[u];
                    } else {
#pragma unroll
                        for (int u = 0; u < 8; u++)
                            sOut[wl][cg * 8 + u] = fmaxf(sOut[wl][cg * 8 + u], v[u]);
                    }
                }
            }
        }
        __syncwarp();
        for (int c0 = lane; c0 < 64; c0 += 32)
            g_feat1[(size_t)q * 64 + c0] = sOut[wl][c0];
        return;
    }

    // ---- role 3: ball2 (polls fps2 progress) ----
    {
        const int lane = threadIdx.x & 31;
        const int wl = threadIdx.x >> 5;
        const int tq = (bid - NB_FPS - NB_S1) * 8 + wl;   // 0..2047
        const int b = tq & 3;
        const int s = tq >> 2;                            // 0..511
        const int q = (b << 9) | s;

        wait_prog(&g_prog2[b], s + 1);

        const float* P = g_qpos1 + (size_t)b * S1 * 3;
        const float* qq = g_qpos2 + (size_t)q * 3;
        float qx = qq[0], qy = qq[1], qz = qq[2];
        int cnt = 0;
        int* out = g_nidx2 + (size_t)q * Kc;
        for (int base = 0; base < S1 && cnt < Kc; base += 32) {
            int i = base + lane;
            const float* p = P + (size_t)i * 3;
            float dx = p[0] - qx, dy = p[1] - qy, dz = p[2] - qz;
            float d = __fmaf_rn(dz, dz, __fmaf_rn(dy, dy, dx * dx));
            bool in = (d <= 1.0f);
            unsigned m = __ballot_sync(FULLMASK, in);
            int pre = __popc(m & ((1u << lane) - 1u));
            int slot = cnt + pre;
            if (in && slot < Kc) out[slot] = i;
            cnt += __popc(m);
        }
        if (cnt > Kc) cnt = Kc;
        for (int j = cnt + lane; j < Kc; j += 32) out[j] = 0;
        if (lane == 0) g_cnt2[q] = cnt;
    }
}

// ---------------- reset: progress counters are stale across graph replays ----------------
__global__ void reset_kernel()
{
    if (threadIdx.x < Bc) { g_prog1[threadIdx.x] = 0; g_prog2[threadIdx.x] = 0; }
}

// ---------------- dense1: 4 independent FFMA2 chains (8 outputs/pass) ----------------
template <int CIN, int COUT>
__device__ __forceinline__ void dense1(const float* h, const float* sW, const float* sB,
                                       float4* __restrict__ o)
{
    static_assert(COUT % 8 == 0, "COUT must be multiple of 8");
#pragma unroll 1
    for (int cg = 0; cg < COUT / 8; cg++) {
        ull a01 = pk2(sB[cg * 8 + 0], sB[cg * 8 + 1]);
        ull a23 = pk2(sB[cg * 8 + 2], sB[cg * 8 + 3]);
        ull a45 = pk2(sB[cg * 8 + 4], sB[cg * 8 + 5]);
        ull a67 = pk2(sB[cg * 8 + 6], sB[cg * 8 + 7]);
#pragma unroll
        for (int k = 0; k < CIN; k++) {
            float4 w0 = *reinterpret_cast<const float4*>(&sW[k * COUT + cg * 8]);
            float4 w1 = *reinterpret_cast<const float4*>(&sW[k * COUT + cg * 8 + 4]);
            ull hh = pk2(h[k], h[k]);
            a01 = fma2_(hh, pk2(w0.x, w0.y), a01);
            a23 = fma2_(hh, pk2(w0.z, w0.w), a23);
            a45 = fma2_(hh, pk2(w1.x, w1.y), a45);
            a67 = fma2_(hh, pk2(w1.z, w1.w), a67);
        }
        float x0, x1, x2, x3, x4, x5, x6, x7;
        upk2(x0, x1, a01); upk2(x2, x3, a23);
        upk2(x4, x5, a45); upk2(x6, x7, a67);
        o[cg * 2]     = make_float4(fmaxf(x0, 0.f), fmaxf(x1, 0.f), fmaxf(x2, 0.f), fmaxf(x3, 0.f));
        o[cg * 2 + 1] = make_float4(fmaxf(x4, 0.f), fmaxf(x5, 0.f), fmaxf(x6, 0.f), fmaxf(x7, 0.f));
    }
}

// ---------------- Stage2 layer A: gather [feat64, dpos3] -> 67->64 ----------------
__global__ void __launch_bounds__(128)
layerA2_kernel(const float* __restrict__ feat1, const float* __restrict__ pos1,
               const float* __restrict__ qpos2, const int* __restrict__ nidx,
               const float* __restrict__ W, const float* __restrict__ Bb,
               float* __restrict__ out)
{
    __shared__ __align__(16) float sW[67 * 64];
    __shared__ float sB[64];
    for (int i = threadIdx.x; i < 67 * 64; i += 128) sW[i] = W[i];
    if (threadIdx.x < 64) sB[threadIdx.x] = Bb[threadIdx.x];
    __syncthreads();

    int t = blockIdx.x * 128 + threadIdx.x;
    int q = t >> 6;
    int b = q >> 9;
    int idx = nidx[t];
    const float* f = feat1 + (size_t)(b * S1 + idx) * 64;
    const float* pp = pos1 + (size_t)(b * S1 + idx) * 3;
    const float* qq = qpos2 + (size_t)q * 3;

    float h0[67];
#pragma unroll
    for (int k = 0; k < 64; k += 4) {
        float4 v = *reinterpret_cast<const float4*>(f + k);
        h0[k] = v.x; h0[k + 1] = v.y; h0[k + 2] = v.z; h0[k + 3] = v.w;
    }
    h0[64] = pp[0] - qq[0]; h0[65] = pp[1] - qq[1]; h0[66] = pp[2] - qq[2];
    dense1<67, 64>(h0, sW, sB, (float4*)(out + (size_t)t * 64));
}

// ---------------- Stage2 layer B: 64->64 ----------------
__global__ void __launch_bounds__(128)
layerB2_kernel(const float* __restrict__ in, const float* __restrict__ W,
               const float* __restrict__ Bb, float* __restrict__ out)
{
    __shared__ __align__(16) float sW[64 * 64];
    __shared__ float sB[64];
    for (int i = threadIdx.x; i < 64 * 64; i += 128) sW[i] = W[i];
    if (threadIdx.x < 64) sB[threadIdx.x] = Bb[threadIdx.x];
    __syncthreads();

    int t = blockIdx.x * 128 + threadIdx.x;
    float h[64];
    const float* f = in + (size_t)t * 64;
#pragma unroll
    for (int k = 0; k < 64; k += 4) {
        float4 v = *reinterpret_cast<const float4*>(f + k);
        h[k] = v.x; h[k + 1] = v.y; h[k + 2] = v.z; h[k + 3] = v.w;
    }
    dense1<64, 64>(h, sW, sB, (float4*)(out + (size_t)t * 64));
}

// ---------------- Stage2 layer C + masked max-pool (warp/query, 2 nbrs/lane) ----------------
template <int C2, int COUT, int NTH, bool TAIL>
__global__ void __launch_bounds__(NTH)
layerC_kernel(const float* __restrict__ in, const int* __restrict__ cnt,
              const float* __restrict__ W, const float* __restrict__ bias,
              float* __restrict__ out, int totalq,
              const float* __restrict__ qpos2, int mode)
{
    constexpr int NW = NTH / 32;
    if (TAIL && (int)blockIdx.x >= totalq / NW) {
        if (mode) {
            int i = ((int)blockIdx.x - totalq / NW) * NTH + threadIdx.x;
            const int featN = Bc * S2 * 128;
            const int posN = Bc * S2 * 3;
            if (i < posN) out[featN + i] = qpos2[i];
            if (mode >= 2 && i < Bc * S2) out[featN + posN + i] = (float)(i / S2);
        }
        return;
    }
    __shared__ __align__(16) float sW[C2 * COUT];
    __shared__ float sB[COUT];
    for (int i = threadIdx.x; i < C2 * COUT; i += NTH) sW[i] = W[i];
    for (int i = threadIdx.x; i < COUT; i += NTH) sB[i] = bias[i];
    __syncthreads();

    int lane = threadIdx.x & 31;
    int wl = threadIdx.x >> 5;
    int q = blockIdx.x * NW + wl;
    if (q >= totalq) return;
    int c = cnt[q];
    bool va = lane < c, vb = lane + 32 < c;

    float ha[C2], hb[C2];
    const float* fa = in + ((size_t)q * Kc + lane) * C2;
    const float* fb = fa + 32 * C2;
#pragma unroll
    for (int k = 0; k < C2; k += 4) {
        float4 u = *reinterpret_cast<const float4*>(fa + k);
        float4 v = *reinterpret_cast<const float4*>(fb + k);
        ha[k] = u.x; ha[k + 1] = u.y; ha[k + 2] = u.z; ha[k + 3] = u.w;
        hb[k] = v.x; hb[k + 1] = v.y; hb[k + 2] = v.z; hb[k + 3] = v.w;
    }

#pragma unroll 1
    for (int cg = 0; cg < COUT / 4; cg++) {
        ull a01 = pk2(sB[cg * 4 + 0], sB[cg * 4 + 1]);
        ull a23 = pk2(sB[cg * 4 + 2], sB[cg * 4 + 3]);
        ull b01 = a01, b23 = a23;
#pragma unroll
        for (int k = 0; k < C2; k++) {
            float4 w = *reinterpret_cast<const float4*>(&sW[k * COUT + cg * 4]);
            ull w01 = pk2(w.x, w.y), w23 = pk2(w.z, w.w);
            ull hA = pk2(ha[k], ha[k]);
            ull hB = pk2(hb[k], hb[k]);
            a01 = fma2_(hA, w01, a01); a23 = fma2_(hA, w23, a23);
            b01 = fma2_(hB, w01, b01); b23 = fma2_(hB, w23, b23);
        }
        float x0, x1, x2, x3, y0, y1, y2, y3;
        upk2(x0, x1, a01); upk2(x2, x3, a23);
        upk2(y0, y1, b01); upk2(y2, y3, b23);
        x0 = va ? fmaxf(x0, 0.f) : -CUDART_INF_F;
        x1 = va ? fmaxf(x1, 0.f) : -CUDART_INF_F;
        x2 = va ? fmaxf(x2, 0.f) : -CUDART_INF_F;
        x3 = va ? fmaxf(x3, 0.f) : -CUDART_INF_F;
        y0 = vb ? fmaxf(y0, 0.f) : -CUDART_INF_F;
        y1 = vb ? fmaxf(y1, 0.f) : -CUDART_INF_F;
        y2 = vb ? fmaxf(y2, 0.f) : -CUDART_INF_F;
        y3 = vb ? fmaxf(y3, 0.f) : -CUDART_INF_F;
        float v0 = fmaxf(x0, y0), v1 = fmaxf(x1, y1);
        float v2 = fmaxf(x2, y2), v3 = fmaxf(x3, y3);
#pragma unroll
        for (int off = 16; off; off >>= 1) {
            v0 = fmaxf(v0, __shfl_down_sync(FULLMASK, v0, off));
            v1 = fmaxf(v1, __shfl_down_sync(FULLMASK, v1, off));
            v2 = fmaxf(v2, __shfl_down_sync(FULLMASK, v2, off));
            v3 = fmaxf(v3, __shfl_down_sync(FULLMASK, v3, off));
        }
        if (lane == 0)
            *reinterpret_cast<float4*>(out + (size_t)q * COUT + cg * 4) =
                make_float4(v0, v1, v2, v3);
    }
}

extern "C" void kernel_launch(void* const* d_in, const int* in_sizes, int n_in,
                              void* d_out, int out_size)
{
    const float* x   = (const float*)d_in[0];
    const float* w1a = (const float*)d_in[1];  const float* b1a = (const float*)d_in[2];
    const float* w1b = (const float*)d_in[3];  const float* b1b = (const float*)d_in[4];
    const float* w1c = (const float*)d_in[5];  const float* b1c = (const float*)d_in[6];
    const float* w2a = (const float*)d_in[7];  const float* b2a = (const float*)d_in[8];
    const float* w2b = (const float*)d_in[9];  const float* b2b = (const float*)d_in[10];
    const float* w2c = (const float*)d_in[11]; const float* b2c = (const float*)d_in[12];
    float* out = (float*)d_out;

    void *pq1, *pq2, *pn2, *pc2, *pf1, *pa, *pb;
    cudaGetSymbolAddress(&pq1, g_qpos1);
    cudaGetSymbolAddress(&pq2, g_qpos2);
    cudaGetSymbolAddress(&pn2, g_nidx2);
    cudaGetSymbolAddress(&pc2, g_cnt2);
    cudaGetSymbolAddress(&pf1, g_feat1);
    cudaGetSymbolAddress(&pa, g_bufA);
    cudaGetSymbolAddress(&pb, g_bufB);
    float* qpos1 = (float*)pq1;  float* qpos2 = (float*)pq2;
    int* nidx2 = (int*)pn2;      int* cnt2 = (int*)pc2;
    float* feat1 = (float*)pf1;  float* bufA = (float*)pa;  float* bufB = (float*)pb;

    const int featN = Bc * S2 * 128;
    const int posN = Bc * S2 * 3;
    int mode = 0;
    if (out_size >= featN + posN) mode = 1;
    if (out_size >= featN + posN + Bc * S2) mode = 2;

    // K0: reset progress counters (stale across graph replays)
    reset_kernel<<<1, 32>>>();

    // K1: mega — fps1+fps2 producers || stage1 per-query pipeline || ball2
    mega_kernel<<<NB_MEGA, 256>>>(x, w1a, b1a, w1b, b1b, w1c, b1c);

    // K2/K3: stage2 MLP A, B
    layerA2_kernel<<<(Bc * S2 * Kc) / 128, 128>>>(feat1, qpos1, qpos2, nidx2, w2a, b2a, bufA);
    layerB2_kernel<<<(Bc * S2 * Kc) / 128, 128>>>(bufA, w2b, b2b, bufB);

    // K4: stage2 layer C + maxpool, with tail blocks for optional pos/batch outputs
    {
        int nq = (Bc * S2) / 4;
        int tailBlks = (posN + 127) / 128 + 1;
        layerC_kernel<64, 128, 128, true><<<nq + tailBlks, 128>>>(
            bufB, cnt2, w2c, b2c, out, Bc * S2, qpos2, mode);
    }
}

// round 15
// speedup vs baseline: 1.3014x; 1.3014x over previous
#include <cuda_runtime.h>
#include <math_constants.h>

#define FULLMASK 0xffffffffu
typedef unsigned long long ull;

static constexpr int Bc = 4;
static constexpr int Nc = 4096;
static constexpr int S1 = 2048;
static constexpr int S2 = 512;
static constexpr int Kc = 64;

// ---------------- scratch (device globals; no allocation allowed) ----------------
__device__ float g_qpos1[Bc * S1 * 3];
__device__ float g_qpos2[Bc * S2 * 3];
__device__ int   g_nidx2[Bc * S2 * Kc];
__device__ int   g_cnt2[Bc * S2];
__device__ float g_feat1[Bc * S1 * 64];
__device__ float g_bufA[Bc * S2 * Kc * 64];
__device__ float g_bufB[Bc * S2 * Kc * 64];
// progress counters (reset each run by reset_kernel — stale across graph replays!)
__device__ int g_prog1[Bc];
__device__ int g_prog2[Bc];

// ---------------- packed f32x2 helpers ----------------
__device__ __forceinline__ ull pk2(float lo, float hi) {
    ull r; asm("mov.b64 %0, {%1, %2};" : "=l"(r) : "f"(lo), "f"(hi)); return r;
}
__device__ __forceinline__ void upk2(float& lo, float& hi, ull v) {
    asm("mov.b64 {%0, %1}, %2;" : "=f"(lo), "=f"(hi) : "l"(v));
}
__device__ __forceinline__ ull fma2_(ull a, ull b, ull c) {
    ull d; asm("fma.rn.f32x2 %0, %1, %2, %3;" : "=l"(d) : "l"(a), "l"(b), "l"(c)); return d;
}
__device__ __forceinline__ ull add2_(ull a, ull b) {
    ull d; asm("add.rn.f32x2 %0, %1, %2;" : "=l"(d) : "l"(a), "l"(b)); return d;
}

// ---------------- FPS body: __syncthreads + REDUX (proven R8/R11 core) ----------------
// Points cached in DYNAMIC smem as float4(x,y,z,|p|^2): 29cyc winner lookup.
// Publishes progress every (pubmask+1) steps (threadfence + volatile store) so
// consumer blocks can start per-query work while FPS runs.
// NOTE: volatile spin-sync INSIDE fps regressed +1.27ms (R9/R10). Do not retry.
// NOTE: co-residency with consumer CTAs regressed +281us (R12/13) — mega kernel
// must force occupancy 1 so producer blocks own their SM.
template <int NPT, int NTH>
__device__ __forceinline__ void fps_body(const float* __restrict__ P, int pstride,
                                         int n, int nsamp, float* __restrict__ qpos,
                                         float4* __restrict__ spts,
                                         int* prog, int pubmask)
{
    constexpr int NW = NTH / 32;
    __shared__ ull skey[2][NW];
    const int t = threadIdx.x, lane = t & 31, warp = t >> 5;

    ull px2[NPT / 2], py2[NPT / 2], pz2[NPT / 2], nr2[NPT / 2];
    float md[NPT];
    const int i0 = t * NPT;
#pragma unroll
    for (int k2 = 0; k2 < NPT / 2; k2++) {
        const float* pA = P + (size_t)(i0 + 2 * k2) * pstride;
        const float* pB = pA + pstride;
        float ax = pA[0], ay = pA[1], az = pA[2];
        float bx = pB[0], by = pB[1], bz = pB[2];
        float na = __fmaf_rn(az, az, __fmaf_rn(ay, ay, ax * ax));
        float nb = __fmaf_rn(bz, bz, __fmaf_rn(by, by, bx * bx));
        px2[k2] = pk2(ax, bx); py2[k2] = pk2(ay, by);
        pz2[k2] = pk2(az, bz); nr2[k2] = pk2(na, nb);
        spts[i0 + 2 * k2]     = make_float4(ax, ay, az, na);
        spts[i0 + 2 * k2 + 1] = make_float4(bx, by, bz, nb);
        md[2 * k2] = CUDART_INF_F; md[2 * k2 + 1] = CUDART_INF_F;
    }
    __syncthreads();
    float4 c = spts[0];
    if (t == 0) { qpos[0] = c.x; qpos[1] = c.y; qpos[2] = c.z; }

    for (int step = 1; step < nsamp; step++) {
        const ull KX = pk2(-2.f * c.x, -2.f * c.x);
        const ull KY = pk2(-2.f * c.y, -2.f * c.y);
        const ull KZ = pk2(-2.f * c.z, -2.f * c.z);
        const ull CC = pk2(c.w, c.w);
        float bm = -CUDART_INF_F; int bi = 0;
#pragma unroll
        for (int k2 = 0; k2 < NPT / 2; k2++) {
            ull e = fma2_(pz2[k2], KZ, nr2[k2]);
            e = fma2_(py2[k2], KY, e);
            e = fma2_(px2[k2], KX, e);
            e = add2_(e, CC);
            float e0, e1; upk2(e0, e1, e);
            float m0 = fminf(md[2 * k2], e0);     md[2 * k2] = m0;
            float m1 = fminf(md[2 * k2 + 1], e1); md[2 * k2 + 1] = m1;
            if (m0 > bm) { bm = m0; bi = i0 + 2 * k2; }
            if (m1 > bm) { bm = m1; bi = i0 + 2 * k2 + 1; }
        }
        bm = fmaxf(bm, 0.0f);   // keep unsigned bit order valid
        unsigned hbits = __float_as_uint(bm);
        unsigned hmax = __reduce_max_sync(FULLMASK, hbits);
        unsigned locand = (hbits == hmax) ? (unsigned)(n - 1 - bi) : 0u;
        unsigned lomax = __reduce_max_sync(FULLMASK, locand);
        if (lane == 0) skey[step & 1][warp] = ((ull)hmax << 32) | lomax;
        __syncthreads();
        ull best = skey[step & 1][0];
#pragma unroll
        for (int w = 1; w < NW; w++) {
            ull o = skey[step & 1][w];
            if (o > best) best = o;
        }
        int wi = n - 1 - (int)(unsigned)(best & 0xffffffffull);
        c = spts[wi];
        if (t == 0) {
            float* o = qpos + (size_t)step * 3;
            o[0] = c.x; o[1] = c.y; o[2] = c.z;
            if ((step & pubmask) == 0 || step == nsamp - 1) {
                __threadfence();
                *(volatile int*)prog = step + 1;
            }
        }
    }
}

// ---------------- consumer wait: poll + acquire fence ----------------
__device__ __forceinline__ void wait_prog(const int* p, int need)
{
    while (*(volatile const int*)p < need) __nanosleep(256);
    __threadfence();
}

// ---------------- mega kernel: fps1+fps2 || per-query stage1 pipeline || ball2 ----------------
// Launched with 120KB dynamic smem to FORCE occupancy 1 CTA/SM: producer blocks
// (bids 0..3, wave-1 deterministic placement) run with zero co-resident contention.
static constexpr int NB_FPS = Bc;                  // 4
static constexpr int NB_S1  = (Bc * S1) / 8;       // 1024 (8 warps/block, 1 query/warp)
static constexpr int NB_B2  = (Bc * S2) / 8;       // 256
static constexpr int NB_MEGA = NB_FPS + NB_S1 + NB_B2;   // 1284

__global__ void __launch_bounds__(256)
mega_kernel(const float* __restrict__ x,
            const float* __restrict__ W1, const float* __restrict__ B1,
            const float* __restrict__ W2, const float* __restrict__ B2,
            const float* __restrict__ WC, const float* __restrict__ BC)
{
    extern __shared__ float4 dsm[];       // producer point cache (64KB for fps1)
    const int bid = blockIdx.x;

    // ---- role 1: FPS producer (one CTA per batch; fps1 then fps2) ----
    if (bid < NB_FPS) {
        const int b = bid;
        fps_body<16, 256>(x + (size_t)b * Nc * 6, 6, Nc, S1,
                          g_qpos1 + (size_t)b * S1 * 3, dsm, &g_prog1[b], 15);
        __syncthreads();   // t0's final qpos1 writes visible before fps2 reloads
        fps_body<8, 256>(g_qpos1 + (size_t)b * S1 * 3, 3, S1, S2,
                         g_qpos2 + (size_t)b * S2 * 3, dsm, &g_prog2[b], 7);
        return;
    }

    // ---- role 2: stage-1 per-query pipeline: poll -> ball -> MLP -> maxpool ----
    if (bid < NB_FPS + NB_S1) {
        __shared__ __align__(16) float sW1[6 * 32];
        __shared__ float sB1[32];
        __shared__ __align__(16) float sW2[32 * 32];
        __shared__ float sB2[32];
        __shared__ __align__(16) float sWC[32 * 64];
        __shared__ float sBC[64];
        __shared__ int   snidx[8][Kc];
        __shared__ float sOut[8][64];
        for (int i = threadIdx.x; i < 6 * 32; i += 256) sW1[i] = W1[i];
        if (threadIdx.x < 32) { sB1[threadIdx.x] = B1[threadIdx.x]; sB2[threadIdx.x] = B2[threadIdx.x]; }
        for (int i = threadIdx.x; i < 32 * 32; i += 256) sW2[i] = W2[i];
        for (int i = threadIdx.x; i < 32 * 64; i += 256) sWC[i] = WC[i];
        if (threadIdx.x < 64) sBC[threadIdx.x] = BC[threadIdx.x];
        __syncthreads();

        const int lane = threadIdx.x & 31;
        const int wl = threadIdx.x >> 5;
        // round-robin batch mapping: consumer residency order tracks all 4
        // parallel fps CTAs' production frontier
        const int tq = (bid - NB_FPS) * 8 + wl;       // 0..8191
        const int b = tq & 3;
        const int s = tq >> 2;                        // 0..2047
        const int q = (b << 11) | s;

        wait_prog(&g_prog1[b], s + 1);

        const float* qq = g_qpos1 + (size_t)q * 3;
        const float qx = qq[0], qy = qq[1], qz = qq[2];

        // ball query (first 64 in-range by ascending index) — idx stays in smem
        const float* P = x + (size_t)b * Nc * 6;
        int cnt = 0;
        for (int base = 0; base < Nc && cnt < Kc; base += 32) {
            int i = base + lane;
            const float* p = P + (size_t)i * 6;
            float dx = p[0] - qx, dy = p[1] - qy, dz = p[2] - qz;
            float d = __fmaf_rn(dz, dz, __fmaf_rn(dy, dy, dx * dx));
            bool in = (d <= 0.25f);
            unsigned m = __ballot_sync(FULLMASK, in);
            int pre = __popc(m & ((1u << lane) - 1u));
            int slot = cnt + pre;
            if (in && slot < Kc) snidx[wl][slot] = i;
            cnt += __popc(m);
        }
        if (cnt > Kc) cnt = Kc;
        for (int j = cnt + lane; j < Kc; j += 32) snidx[wl][j] = 0;
        __syncwarp();

        // fused gather -> 6->32 -> 32->32 -> 32->64 -> masked maxpool
#pragma unroll 1
        for (int r = 0; r < 2; r++) {
            int j = r * 32 + lane;
            int idx = snidx[wl][j];
            const float* rp = P + (size_t)idx * 6;
            float h0[6] = { rp[3], rp[4], rp[5], rp[0] - qx, rp[1] - qy, rp[2] - qz };
            float h1[32];
#pragma unroll 1
            for (int cg = 0; cg < 4; cg++) {
                ull a01 = pk2(sB1[cg * 8 + 0], sB1[cg * 8 + 1]);
                ull a23 = pk2(sB1[cg * 8 + 2], sB1[cg * 8 + 3]);
                ull a45 = pk2(sB1[cg * 8 + 4], sB1[cg * 8 + 5]);
                ull a67 = pk2(sB1[cg * 8 + 6], sB1[cg * 8 + 7]);
#pragma unroll
                for (int k = 0; k < 6; k++) {
                    float4 w0 = *reinterpret_cast<const float4*>(&sW1[k * 32 + cg * 8]);
                    float4 w1 = *reinterpret_cast<const float4*>(&sW1[k * 32 + cg * 8 + 4]);
                    ull hh = pk2(h0[k], h0[k]);
                    a01 = fma2_(hh, pk2(w0.x, w0.y), a01);
                    a23 = fma2_(hh, pk2(w0.z, w0.w), a23);
                    a45 = fma2_(hh, pk2(w1.x, w1.y), a45);
                    a67 = fma2_(hh, pk2(w1.z, w1.w), a67);
                }
                float v0,v1,v2,v3,v4,v5,v6,v7;
                upk2(v0, v1, a01); upk2(v2, v3, a23);
                upk2(v4, v5, a45); upk2(v6, v7, a67);
                h1[cg*8+0]=fmaxf(v0,0.f); h1[cg*8+1]=fmaxf(v1,0.f);
                h1[cg*8+2]=fmaxf(v2,0.f); h1[cg*8+3]=fmaxf(v3,0.f);
                h1[cg*8+4]=fmaxf(v4,0.f); h1[cg*8+5]=fmaxf(v5,0.f);
                h1[cg*8+6]=fmaxf(v6,0.f); h1[cg*8+7]=fmaxf(v7,0.f);
            }
            float h2[32];
#pragma unroll 1
            for (int cg = 0; cg < 4; cg++) {
                ull a01 = pk2(sB2[cg * 8 + 0], sB2[cg * 8 + 1]);
                ull a23 = pk2(sB2[cg * 8 + 2], sB2[cg * 8 + 3]);
                ull a45 = pk2(sB2[cg * 8 + 4], sB2[cg * 8 + 5]);
                ull a67 = pk2(sB2[cg * 8 + 6], sB2[cg * 8 + 7]);
#pragma unroll
                for (int k = 0; k < 32; k++) {
                    float4 w0 = *reinterpret_cast<const float4*>(&sW2[k * 32 + cg * 8]);
                    float4 w1 = *reinterpret_cast<const float4*>(&sW2[k * 32 + cg * 8 + 4]);
                    ull hh = pk2(h1[k], h1[k]);
                    a01 = fma2_(hh, pk2(w0.x, w0.y), a01);
                    a23 = fma2_(hh, pk2(w0.z, w0.w), a23);
                    a45 = fma2_(hh, pk2(w1.x, w1.y), a45);
                    a67 = fma2_(hh, pk2(w1.z, w1.w), a67);
                }
                float v0,v1,v2,v3,v4,v5,v6,v7;
                upk2(v0, v1, a01); upk2(v2, v3, a23);
                upk2(v4, v5, a45); upk2(v6, v7, a67);
                h2[cg*8+0]=fmaxf(v0,0.f); h2[cg*8+1]=fmaxf(v1,0.f);
                h2[cg*8+2]=fmaxf(v2,0.f); h2[cg*8+3]=fmaxf(v3,0.f);
                h2[cg*8+4]=fmaxf(v4,0.f); h2[cg*8+5]=fmaxf(v5,0.f);
                h2[cg*8+6]=fmaxf(v6,0.f); h2[cg*8+7]=fmaxf(v7,0.f);
            }
            bool valid = (j < cnt);
#pragma unroll 1
            for (int cg = 0; cg < 8; cg++) {
                ull a01 = pk2(sBC[cg * 8 + 0], sBC[cg * 8 + 1]);
                ull a23 = pk2(sBC[cg * 8 + 2], sBC[cg * 8 + 3]);
                ull a45 = pk2(sBC[cg * 8 + 4], sBC[cg * 8 + 5]);
                ull a67 = pk2(sBC[cg * 8 + 6], sBC[cg * 8 + 7]);
#pragma unroll
                for (int k = 0; k < 32; k++) {
                    float4 w0 = *reinterpret_cast<const float4*>(&sWC[k * 64 + cg * 8]);
                    float4 w1 = *reinterpret_cast<const float4*>(&sWC[k * 64 + cg * 8 + 4]);
                    ull hh = pk2(h2[k], h2[k]);
                    a01 = fma2_(hh, pk2(w0.x, w0.y), a01);
                    a23 = fma2_(hh, pk2(w0.z, w0.w), a23);
                    a45 = fma2_(hh, pk2(w1.x, w1.y), a45);
                    a67 = fma2_(hh, pk2(w1.z, w1.w), a67);
                }
                float v[8];
                upk2(v[0], v[1], a01); upk2(v[2], v[3], a23);
                upk2(v[4], v[5], a45); upk2(v[6], v[7], a67);
#pragma unroll
                for (int u = 0; u < 8; u++) {
                    float vv = valid ? fmaxf(v[u], 0.f) : -CUDART_INF_F;
#pragma unroll
                    for (int off = 16; off; off >>= 1)
                        vv = fmaxf(vv, __shfl_down_sync(FULLMASK, vv, off));
                    v[u] = vv;
                }
                if (lane == 0) {
                    if (r == 0) {
#pragma unroll
                        for (int u = 0; u < 8; u++) sOut[wl][cg * 8 + u] = v[u];
                    } else {
#pragma unroll
                        for (int u = 0; u < 8; u++)
                            sOut[wl][cg * 8 + u] = fmaxf(sOut[wl][cg * 8 + u], v[u]);
                    }
                }
            }
        }
        __syncwarp();
        for (int c0 = lane; c0 < 64; c0 += 32)
            g_feat1[(size_t)q * 64 + c0] = sOut[wl][c0];
        return;
    }

    // ---- role 3: ball2 (polls fps2 progress) ----
    {
        const int lane = threadIdx.x & 31;
        const int wl = threadIdx.x >> 5;
        const int tq = (bid - NB_FPS - NB_S1) * 8 + wl;   // 0..2047
        const int b = tq & 3;
        const int s = tq >> 2;                            // 0..511
        const int q = (b << 9) | s;

        wait_prog(&g_prog2[b], s + 1);

        const float* P = g_qpos1 + (size_t)b * S1 * 3;
        const float* qq = g_qpos2 + (size_t)q * 3;
        float qx = qq[0], qy = qq[1], qz = qq[2];
        int cnt = 0;
        int* out = g_nidx2 + (size_t)q * Kc;
        for (int base = 0; base < S1 && cnt < Kc; base += 32) {
            int i = base + lane;
            const float* p = P + (size_t)i * 3;
            float dx = p[0] - qx, dy = p[1] - qy, dz = p[2] - qz;
            float d = __fmaf_rn(dz, dz, __fmaf_rn(dy, dy, dx * dx));
            bool in = (d <= 1.0f);
            unsigned m = __ballot_sync(FULLMASK, in);
            int pre = __popc(m & ((1u << lane) - 1u));
            int slot = cnt + pre;
            if (in && slot < Kc) out[slot] = i;
            cnt += __popc(m);
        }
        if (cnt > Kc) cnt = Kc;
        for (int j = cnt + lane; j < Kc; j += 32) out[j] = 0;
        if (lane == 0) g_cnt2[q] = cnt;
    }
}

// ---------------- reset: progress counters are stale across graph replays ----------------
__global__ void reset_kernel()
{
    if (threadIdx.x < Bc) { g_prog1[threadIdx.x] = 0; g_prog2[threadIdx.x] = 0; }
}

// ---------------- dense1: 4 independent FFMA2 chains (8 outputs/pass) ----------------
template <int CIN, int COUT>
__device__ __forceinline__ void dense1(const float* h, const float* sW, const float* sB,
                                       float4* __restrict__ o)
{
    static_assert(COUT % 8 == 0, "COUT must be multiple of 8");
#pragma unroll 1
    for (int cg = 0; cg < COUT / 8; cg++) {
        ull a01 = pk2(sB[cg * 8 + 0], sB[cg * 8 + 1]);
        ull a23 = pk2(sB[cg * 8 + 2], sB[cg * 8 + 3]);
        ull a45 = pk2(sB[cg * 8 + 4], sB[cg * 8 + 5]);
        ull a67 = pk2(sB[cg * 8 + 6], sB[cg * 8 + 7]);
#pragma unroll
        for (int k = 0; k < CIN; k++) {
            float4 w0 = *reinterpret_cast<const float4*>(&sW[k * COUT + cg * 8]);
            float4 w1 = *reinterpret_cast<const float4*>(&sW[k * COUT + cg * 8 + 4]);
            ull hh = pk2(h[k], h[k]);
            a01 = fma2_(hh, pk2(w0.x, w0.y), a01);
            a23 = fma2_(hh, pk2(w0.z, w0.w), a23);
            a45 = fma2_(hh, pk2(w1.x, w1.y), a45);
            a67 = fma2_(hh, pk2(w1.z, w1.w), a67);
        }
        float x0, x1, x2, x3, x4, x5, x6, x7;
        upk2(x0, x1, a01); upk2(x2, x3, a23);
        upk2(x4, x5, a45); upk2(x6, x7, a67);
        o[cg * 2]     = make_float4(fmaxf(x0, 0.f), fmaxf(x1, 0.f), fmaxf(x2, 0.f), fmaxf(x3, 0.f));
        o[cg * 2 + 1] = make_float4(fmaxf(x4, 0.f), fmaxf(x5, 0.f), fmaxf(x6, 0.f), fmaxf(x7, 0.f));
    }
}

// ---------------- Stage2 layer A: gather [feat64, dpos3] -> 67->64 ----------------
__global__ void __launch_bounds__(128)
layerA2_kernel(const float* __restrict__ feat1, const float* __restrict__ pos1,
               const float* __restrict__ qpos2, const int* __restrict__ nidx,
               const float* __restrict__ W, const float* __restrict__ Bb,
               float* __restrict__ out)
{
    __shared__ __align__(16) float sW[67 * 64];
    __shared__ float sB[64];
    for (int i = threadIdx.x; i < 67 * 64; i += 128) sW[i] = W[i];
    if (threadIdx.x < 64) sB[threadIdx.x] = Bb[threadIdx.x];
    __syncthreads();

    int t = blockIdx.x * 128 + threadIdx.x;
    int q = t >> 6;
    int b = q >> 9;
    int idx = nidx[t];
    const float* f = feat1 + (size_t)(b * S1 + idx) * 64;
    const float* pp = pos1 + (size_t)(b * S1 + idx) * 3;
    const float* qq = qpos2 + (size_t)q * 3;

    float h0[67];
#pragma unroll
    for (int k = 0; k < 64; k += 4) {
        float4 v = *reinterpret_cast<const float4*>(f + k);
        h0[k] = v.x; h0[k + 1] = v.y; h0[k + 2] = v.z; h0[k + 3] = v.w;
    }
    h0[64] = pp[0] - qq[0]; h0[65] = pp[1] - qq[1]; h0[66] = pp[2] - qq[2];
    dense1<67, 64>(h0, sW, sB, (float4*)(out + (size_t)t * 64));
}

// ---------------- Stage2 layer B: 64->64 ----------------
__global__ void __launch_bounds__(128)
layerB2_kernel(const float* __restrict__ in, const float* __restrict__ W,
               const float* __restrict__ Bb, float* __restrict__ out)
{
    __shared__ __align__(16) float sW[64 * 64];
    __shared__ float sB[64];
    for (int i = threadIdx.x; i < 64 * 64; i += 128) sW[i] = W[i];
    if (threadIdx.x < 64) sB[threadIdx.x] = Bb[threadIdx.x];
    __syncthreads();

    int t = blockIdx.x * 128 + threadIdx.x;
    float h[64];
    const float* f = in + (size_t)t * 64;
#pragma unroll
    for (int k = 0; k < 64; k += 4) {
        float4 v = *reinterpret_cast<const float4*>(f + k);
        h[k] = v.x; h[k + 1] = v.y; h[k + 2] = v.z; h[k + 3] = v.w;
    }
    dense1<64, 64>(h, sW, sB, (float4*)(out + (size_t)t * 64));
}

// ---------------- Stage2 layer C + masked max-pool (warp/query, 2 nbrs/lane) ----------------
template <int C2, int COUT, int NTH, bool TAIL>
__global__ void __launch_bounds__(NTH)
layerC_kernel(const float* __restrict__ in, const int* __restrict__ cnt,
              const float* __restrict__ W, const float* __restrict__ bias,
              float* __restrict__ out, int totalq,
              const float* __restrict__ qpos2, int mode)
{
    constexpr int NW = NTH / 32;
    if (TAIL && (int)blockIdx.x >= totalq / NW) {
        if (mode) {
            int i = ((int)blockIdx.x - totalq / NW) * NTH + threadIdx.x;
            const int featN = Bc * S2 * 128;
            const int posN = Bc * S2 * 3;
            if (i < posN) out[featN + i] = qpos2[i];
            if (mode >= 2 && i < Bc * S2) out[featN + posN + i] = (float)(i / S2);
        }
        return;
    }
    __shared__ __align__(16) float sW[C2 * COUT];
    __shared__ float sB[COUT];
    for (int i = threadIdx.x; i < C2 * COUT; i += NTH) sW[i] = W[i];
    for (int i = threadIdx.x; i < COUT; i += NTH) sB[i] = bias[i];
    __syncthreads();

    int lane = threadIdx.x & 31;
    int wl = threadIdx.x >> 5;
    int q = blockIdx.x * NW + wl;
    if (q >= totalq) return;
    int c = cnt[q];
    bool va = lane < c, vb = lane + 32 < c;

    float ha[C2], hb[C2];
    const float* fa = in + ((size_t)q * Kc + lane) * C2;
    const float* fb = fa + 32 * C2;
#pragma unroll
    for (int k = 0; k < C2; k += 4) {
        float4 u = *reinterpret_cast<const float4*>(fa + k);
        float4 v = *reinterpret_cast<const float4*>(fb + k);
        ha[k] = u.x; ha[k + 1] = u.y; ha[k + 2] = u.z; ha[k + 3] = u.w;
        hb[k] = v.x; hb[k + 1] = v.y; hb[k + 2] = v.z; hb[k + 3] = v.w;
    }

#pragma unroll 1
    for (int cg = 0; cg < COUT / 4; cg++) {
        ull a01 = pk2(sB[cg * 4 + 0], sB[cg * 4 + 1]);
        ull a23 = pk2(sB[cg * 4 + 2], sB[cg * 4 + 3]);
        ull b01 = a01, b23 = a23;
#pragma unroll
        for (int k = 0; k < C2; k++) {
            float4 w = *reinterpret_cast<const float4*>(&sW[k * COUT + cg * 4]);
            ull w01 = pk2(w.x, w.y), w23 = pk2(w.z, w.w);
            ull hA = pk2(ha[k], ha[k]);
            ull hB = pk2(hb[k], hb[k]);
            a01 = fma2_(hA, w01, a01); a23 = fma2_(hA, w23, a23);
            b01 = fma2_(hB, w01, b01); b23 = fma2_(hB, w23, b23);
        }
        float x0, x1, x2, x3, y0, y1, y2, y3;
        upk2(x0, x1, a01); upk2(x2, x3, a23);
        upk2(y0, y1, b01); upk2(y2, y3, b23);
        x0 = va ? fmaxf(x0, 0.f) : -CUDART_INF_F;
        x1 = va ? fmaxf(x1, 0.f) : -CUDART_INF_F;
        x2 = va ? fmaxf(x2, 0.f) : -CUDART_INF_F;
        x3 = va ? fmaxf(x3, 0.f) : -CUDART_INF_F;
        y0 = vb ? fmaxf(y0, 0.f) : -CUDART_INF_F;
        y1 = vb ? fmaxf(y1, 0.f) : -CUDART_INF_F;
        y2 = vb ? fmaxf(y2, 0.f) : -CUDART_INF_F;
        y3 = vb ? fmaxf(y3, 0.f) : -CUDART_INF_F;
        float v0 = fmaxf(x0, y0), v1 = fmaxf(x1, y1);
        float v2 = fmaxf(x2, y2), v3 = fmaxf(x3, y3);
#pragma unroll
        for (int off = 16; off; off >>= 1) {
            v0 = fmaxf(v0, __shfl_down_sync(FULLMASK, v0, off));
            v1 = fmaxf(v1, __shfl_down_sync(FULLMASK, v1, off));
            v2 = fmaxf(v2, __shfl_down_sync(FULLMASK, v2, off));
            v3 = fmaxf(v3, __shfl_down_sync(FULLMASK, v3, off));
        }
        if (lane == 0)
            *reinterpret_cast<float4*>(out + (size_t)q * COUT + cg * 4) =
                make_float4(v0, v1, v2, v3);
    }
}

extern "C" void kernel_launch(void* const* d_in, const int* in_sizes, int n_in,
                              void* d_out, int out_size)
{
    const float* x   = (const float*)d_in[0];
    const float* w1a = (const float*)d_in[1];  const float* b1a = (const float*)d_in[2];
    const float* w1b = (const float*)d_in[3];  const float* b1b = (const float*)d_in[4];
    const float* w1c = (const float*)d_in[5];  const float* b1c = (const float*)d_in[6];
    const float* w2a = (const float*)d_in[7];  const float* b2a = (const float*)d_in[8];
    const float* w2b = (const float*)d_in[9];  const float* b2b = (const float*)d_in[10];
    const float* w2c = (const float*)d_in[11]; const float* b2c = (const float*)d_in[12];
    float* out = (float*)d_out;

    void *pq1, *pq2, *pn2, *pc2, *pf1, *pa, *pb;
    cudaGetSymbolAddress(&pq1, g_qpos1);
    cudaGetSymbolAddress(&pq2, g_qpos2);
    cudaGetSymbolAddress(&pn2, g_nidx2);
    cudaGetSymbolAddress(&pc2, g_cnt2);
    cudaGetSymbolAddress(&pf1, g_feat1);
    cudaGetSymbolAddress(&pa, g_bufA);
    cudaGetSymbolAddress(&pb, g_bufB);
    float* qpos1 = (float*)pq1;  float* qpos2 = (float*)pq2;
    int* nidx2 = (int*)pn2;      int* cnt2 = (int*)pc2;
    float* feat1 = (float*)pf1;  float* bufA = (float*)pa;  float* bufB = (float*)pb;

    const int featN = Bc * S2 * 128;
    const int posN = Bc * S2 * 3;
    int mode = 0;
    if (out_size >= featN + posN) mode = 1;
    if (out_size >= featN + posN + Bc * S2) mode = 2;

    // 120KB dynamic smem: holds fps1's 64KB point cache AND forces occupancy 1
    // (120KB dyn + ~18KB static > 228KB/2), so producer CTAs own their SMs.
    const int MEGA_SMEM = 120 * 1024;
    cudaFuncSetAttribute((const void*)mega_kernel,
                         cudaFuncAttributeMaxDynamicSharedMemorySize, MEGA_SMEM);

    // K0: reset progress counters (stale across graph replays)
    reset_kernel<<<1, 32>>>();

    // K1: mega — fps1+fps2 producers || stage1 per-query pipeline || ball2
    mega_kernel<<<NB_MEGA, 256, MEGA_SMEM>>>(x, w1a, b1a, w1b, b1b, w1c, b1c);

    // K2/K3: stage2 MLP A, B
    layerA2_kernel<<<(Bc * S2 * Kc) / 128, 128>>>(feat1, qpos1, qpos2, nidx2, w2a, b2a, bufA);
    layerB2_kernel<<<(Bc * S2 * Kc) / 128, 128>>>(bufA, w2b, b2b, bufB);

    // K4: stage2 layer C + maxpool, with tail blocks for optional pos/batch outputs
    {
        int nq = (Bc * S2) / 4;
        int tailBlks = (posN + 127) / 128 + 1;
        layerC_kernel<64, 128, 128, true><<<nq + tailBlks, 128>>>(
            bufB, cnt2, w2c, b2c, out, Bc * S2, qpos2, mode);
    }
}

// round 17
// speedup vs baseline: 1.3845x; 1.0638x over previous
#include <cuda_runtime.h>
#include <math_constants.h>

#define FULLMASK 0xffffffffu
typedef unsigned long long ull;

static constexpr int Bc = 4;
static constexpr int Nc = 4096;
static constexpr int S1 = 2048;
static constexpr int S2 = 512;
static constexpr int Kc = 64;

// ---------------- scratch (device globals; no allocation allowed) ----------------
__device__ float g_qpos1[Bc * S1 * 3];
__device__ float g_qpos2[Bc * S2 * 3];
__device__ int   g_nidx2[Bc * S2 * Kc];
__device__ int   g_cnt2[Bc * S2];
__device__ float g_feat1[Bc * S1 * 64];
__device__ float g_bufB[Bc * S2 * Kc * 64];
// progress counters (reset each run by reset_kernel — stale across graph replays!)
__device__ int g_prog1[Bc];
__device__ int g_prog2[Bc];

// ---------------- packed f32x2 helpers ----------------
__device__ __forceinline__ ull pk2(float lo, float hi) {
    ull r; asm("mov.b64 %0, {%1, %2};" : "=l"(r) : "f"(lo), "f"(hi)); return r;
}
__device__ __forceinline__ void upk2(float& lo, float& hi, ull v) {
    asm("mov.b64 {%0, %1}, %2;" : "=f"(lo), "=f"(hi) : "l"(v));
}
__device__ __forceinline__ ull fma2_(ull a, ull b, ull c) {
    ull d; asm("fma.rn.f32x2 %0, %1, %2, %3;" : "=l"(d) : "l"(a), "l"(b), "l"(c)); return d;
}
__device__ __forceinline__ ull add2_(ull a, ull b) {
    ull d; asm("add.rn.f32x2 %0, %1, %2;" : "=l"(d) : "l"(a), "l"(b)); return d;
}

// ---------------- FPS body: __syncthreads + REDUX ----------------
// 512 threads: halves compute phase vs 256 (the dominant per-step term).
// Cross-warp reduce: lane-parallel slot read + 2 REDUX (NW-independent) instead
// of a serial NW-slot scan. Same (value, n-1-idx) max => jnp.argmax tie-break.
// NOTE: volatile spin-sync INSIDE fps regressed +1.27ms (R9/R10). Do not retry.
// NOTE: co-residency with consumer CTAs regressed +281us (R12/13) — occupancy 1
// must be forced so producer blocks own their SM.
template <int NPT, int NTH>
__device__ __forceinline__ void fps_body(const float* __restrict__ P, int pstride,
                                         int n, int nsamp, float* __restrict__ qpos,
                                         float4* __restrict__ spts,
                                         int* prog, int pubmask)
{
    constexpr int NW = NTH / 32;
    __shared__ ull skey[2][NW];
    const int t = threadIdx.x, lane = t & 31, warp = t >> 5;

    ull px2[NPT / 2], py2[NPT / 2], pz2[NPT / 2], nr2[NPT / 2];
    float md[NPT];
    const int i0 = t * NPT;
#pragma unroll
    for (int k2 = 0; k2 < NPT / 2; k2++) {
        const float* pA = P + (size_t)(i0 + 2 * k2) * pstride;
        const float* pB = pA + pstride;
        float ax = pA[0], ay = pA[1], az = pA[2];
        float bx = pB[0], by = pB[1], bz = pB[2];
        float na = __fmaf_rn(az, az, __fmaf_rn(ay, ay, ax * ax));
        float nb = __fmaf_rn(bz, bz, __fmaf_rn(by, by, bx * bx));
        px2[k2] = pk2(ax, bx); py2[k2] = pk2(ay, by);
        pz2[k2] = pk2(az, bz); nr2[k2] = pk2(na, nb);
        spts[i0 + 2 * k2]     = make_float4(ax, ay, az, na);
        spts[i0 + 2 * k2 + 1] = make_float4(bx, by, bz, nb);
        md[2 * k2] = CUDART_INF_F; md[2 * k2 + 1] = CUDART_INF_F;
    }
    __syncthreads();
    float4 c = spts[0];
    if (t == 0) { qpos[0] = c.x; qpos[1] = c.y; qpos[2] = c.z; }

    for (int step = 1; step < nsamp; step++) {
        const ull KX = pk2(-2.f * c.x, -2.f * c.x);
        const ull KY = pk2(-2.f * c.y, -2.f * c.y);
        const ull KZ = pk2(-2.f * c.z, -2.f * c.z);
        const ull CC = pk2(c.w, c.w);
        float bm = -CUDART_INF_F; int bi = 0;
#pragma unroll
        for (int k2 = 0; k2 < NPT / 2; k2++) {
            ull e = fma2_(pz2[k2], KZ, nr2[k2]);
            e = fma2_(py2[k2], KY, e);
            e = fma2_(px2[k2], KX, e);
            e = add2_(e, CC);
            float e0, e1; upk2(e0, e1, e);
            float m0 = fminf(md[2 * k2], e0);     md[2 * k2] = m0;
            float m1 = fminf(md[2 * k2 + 1], e1); md[2 * k2 + 1] = m1;
            if (m0 > bm) { bm = m0; bi = i0 + 2 * k2; }
            if (m1 > bm) { bm = m1; bi = i0 + 2 * k2 + 1; }
        }
        bm = fmaxf(bm, 0.0f);   // keep unsigned bit order valid
        unsigned hbits = __float_as_uint(bm);
        unsigned hmax = __reduce_max_sync(FULLMASK, hbits);
        unsigned locand = (hbits == hmax) ? (unsigned)(n - 1 - bi) : 0u;
        unsigned lomax = __reduce_max_sync(FULLMASK, locand);
        if (lane == 0) skey[step & 1][warp] = ((ull)hmax << 32) | lomax;
        __syncthreads();
        // lane-parallel cross-warp reduce (each slot read by >=1 lane; NW<=32)
        ull v = skey[step & 1][lane & (NW - 1)];
        unsigned hi = (unsigned)(v >> 32);
        unsigned lo = (unsigned)v;
        unsigned h2m = __reduce_max_sync(FULLMASK, hi);
        unsigned cand = (hi == h2m) ? lo : 0u;
        unsigned l2m = __reduce_max_sync(FULLMASK, cand);
        int wi = n - 1 - (int)l2m;
        c = spts[wi];
        if (t == 0) {
            float* o = qpos + (size_t)step * 3;
            o[0] = c.x; o[1] = c.y; o[2] = c.z;
            if ((step & pubmask) == 0 || step == nsamp - 1) {
                __threadfence();
                *(volatile int*)prog = step + 1;
            }
        }
    }
}

// ---------------- consumer wait: poll + acquire fence ----------------
__device__ __forceinline__ void wait_prog(const int* p, int need)
{
    while (*(volatile const int*)p < need) __nanosleep(256);
    __threadfence();
}

// ---------------- mega kernel: fps1+fps2 || per-query stage1 pipeline || ball2 ----------------
// 120KB dynamic smem FORCES occupancy 1 CTA/SM; producer blocks (bids 0..3,
// wave-1 deterministic placement) own their SMs.
static constexpr int NTHM = 512;
static constexpr int NB_FPS = Bc;                   // 4
static constexpr int NB_S1  = (Bc * S1) / 16;       // 512 (16 warps/block, 1 query/warp)
static constexpr int NB_B2  = (Bc * S2) / 16;       // 128
static constexpr int NB_MEGA = NB_FPS + NB_S1 + NB_B2;   // 644

__global__ void __launch_bounds__(NTHM)
mega_kernel(const float* __restrict__ x,
            const float* __restrict__ W1, const float* __restrict__ B1,
            const float* __restrict__ W2, const float* __restrict__ B2,
            const float* __restrict__ WC, const float* __restrict__ BC)
{
    extern __shared__ float4 dsm[];       // producer point cache (64KB for fps1)
    const int bid = blockIdx.x;

    // ---- role 1: FPS producer (one CTA per batch; fps1 then fps2) ----
    if (bid < NB_FPS) {
        const int b = bid;
        fps_body<8, NTHM>(x + (size_t)b * Nc * 6, 6, Nc, S1,
                          g_qpos1 + (size_t)b * S1 * 3, dsm, &g_prog1[b], 15);
        __syncthreads();   // t0's final qpos1 writes visible before fps2 reloads
        fps_body<4, NTHM>(g_qpos1 + (size_t)b * S1 * 3, 3, S1, S2,
                          g_qpos2 + (size_t)b * S2 * 3, dsm, &g_prog2[b], 7);
        return;
    }

    // ---- role 2: stage-1 per-query pipeline: poll -> ball -> MLP -> maxpool ----
    if (bid < NB_FPS + NB_S1) {
        __shared__ __align__(16) float sW1[6 * 32];
        __shared__ float sB1[32];
        __shared__ __align__(16) float sW2[32 * 32];
        __shared__ float sB2[32];
        __shared__ __align__(16) float sWC[32 * 64];
        __shared__ float sBC[64];
        __shared__ int   snidx[16][Kc];
        __shared__ float sOut[16][64];
        for (int i = threadIdx.x; i < 6 * 32; i += NTHM) sW1[i] = W1[i];
        if (threadIdx.x < 32) { sB1[threadIdx.x] = B1[threadIdx.x]; sB2[threadIdx.x] = B2[threadIdx.x]; }
        for (int i = threadIdx.x; i < 32 * 32; i += NTHM) sW2[i] = W2[i];
        for (int i = threadIdx.x; i < 32 * 64; i += NTHM) sWC[i] = WC[i];
        if (threadIdx.x < 64) sBC[threadIdx.x] = BC[threadIdx.x];
        __syncthreads();

        const int lane = threadIdx.x & 31;
        const int wl = threadIdx.x >> 5;
        // round-robin batch mapping: consumer residency order tracks all 4
        // parallel fps CTAs' production frontier
        const int tq = (bid - NB_FPS) * 16 + wl;      // 0..8191
        const int b = tq & 3;
        const int s = tq >> 2;                        // 0..2047
        const int q = (b << 11) | s;

        wait_prog(&g_prog1[b], s + 1);

        const float* qq = g_qpos1 + (size_t)q * 3;
        const float qx = qq[0], qy = qq[1], qz = qq[2];

        // ball query (first 64 in-range by ascending index) — idx stays in smem
        const float* P = x + (size_t)b * Nc * 6;
        int cnt = 0;
        for (int base = 0; base < Nc && cnt < Kc; base += 32) {
            int i = base + lane;
            const float* p = P + (size_t)i * 6;
            float dx = p[0] - qx, dy = p[1] - qy, dz = p[2] - qz;
            float d = __fmaf_rn(dz, dz, __fmaf_rn(dy, dy, dx * dx));
            bool in = (d <= 0.25f);
            unsigned m = __ballot_sync(FULLMASK, in);
            int pre = __popc(m & ((1u << lane) - 1u));
            int slot = cnt + pre;
            if (in && slot < Kc) snidx[wl][slot] = i;
            cnt += __popc(m);
        }
        if (cnt > Kc) cnt = Kc;
        for (int j = cnt + lane; j < Kc; j += 32) snidx[wl][j] = 0;
        __syncwarp();

        // fused gather -> 6->32 -> 32->32 -> 32->64 -> masked maxpool
#pragma unroll 1
        for (int r = 0; r < 2; r++) {
            int j = r * 32 + lane;
            int idx = snidx[wl][j];
            const float* rp = P + (size_t)idx * 6;
            float h0[6] = { rp[3], rp[4], rp[5], rp[0] - qx, rp[1] - qy, rp[2] - qz };
            float h1[32];
#pragma unroll 1
            for (int cg = 0; cg < 4; cg++) {
                ull a01 = pk2(sB1[cg * 8 + 0], sB1[cg * 8 + 1]);
                ull a23 = pk2(sB1[cg * 8 + 2], sB1[cg * 8 + 3]);
                ull a45 = pk2(sB1[cg * 8 + 4], sB1[cg * 8 + 5]);
                ull a67 = pk2(sB1[cg * 8 + 6], sB1[cg * 8 + 7]);
#pragma unroll
                for (int k = 0; k < 6; k++) {
                    float4 w0 = *reinterpret_cast<const float4*>(&sW1[k * 32 + cg * 8]);
                    float4 w1 = *reinterpret_cast<const float4*>(&sW1[k * 32 + cg * 8 + 4]);
                    ull hh = pk2(h0[k], h0[k]);
                    a01 = fma2_(hh, pk2(w0.x, w0.y), a01);
                    a23 = fma2_(hh, pk2(w0.z, w0.w), a23);
                    a45 = fma2_(hh, pk2(w1.x, w1.y), a45);
                    a67 = fma2_(hh, pk2(w1.z, w1.w), a67);
                }
                float v0,v1,v2,v3,v4,v5,v6,v7;
                upk2(v0, v1, a01); upk2(v2, v3, a23);
                upk2(v4, v5, a45); upk2(v6, v7, a67);
                h1[cg*8+0]=fmaxf(v0,0.f); h1[cg*8+1]=fmaxf(v1,0.f);
                h1[cg*8+2]=fmaxf(v2,0.f); h1[cg*8+3]=fmaxf(v3,0.f);
                h1[cg*8+4]=fmaxf(v4,0.f); h1[cg*8+5]=fmaxf(v5,0.f);
                h1[cg*8+6]=fmaxf(v6,0.f); h1[cg*8+7]=fmaxf(v7,0.f);
            }
            float h2[32];
#pragma unroll 1
            for (int cg = 0; cg < 4; cg++) {
                ull a01 = pk2(sB2[cg * 8 + 0], sB2[cg * 8 + 1]);
                ull a23 = pk2(sB2[cg * 8 + 2], sB2[cg * 8 + 3]);
                ull a45 = pk2(sB2[cg * 8 + 4], sB2[cg * 8 + 5]);
                ull a67 = pk2(sB2[cg * 8 + 6], sB2[cg * 8 + 7]);
#pragma unroll
                for (int k = 0; k < 32; k++) {
                    float4 w0 = *reinterpret_cast<const float4*>(&sW2[k * 32 + cg * 8]);
                    float4 w1 = *reinterpret_cast<const float4*>(&sW2[k * 32 + cg * 8 + 4]);
                    ull hh = pk2(h1[k], h1[k]);
                    a01 = fma2_(hh, pk2(w0.x, w0.y), a01);
                    a23 = fma2_(hh, pk2(w0.z, w0.w), a23);
                    a45 = fma2_(hh, pk2(w1.x, w1.y), a45);
                    a67 = fma2_(hh, pk2(w1.z, w1.w), a67);
                }
                float v0,v1,v2,v3,v4,v5,v6,v7;
                upk2(v0, v1, a01); upk2(v2, v3, a23);
                upk2(v4, v5, a45); upk2(v6, v7, a67);
                h2[cg*8+0]=fmaxf(v0,0.f); h2[cg*8+1]=fmaxf(v1,0.f);
                h2[cg*8+2]=fmaxf(v2,0.f); h2[cg*8+3]=fmaxf(v3,0.f);
                h2[cg*8+4]=fmaxf(v4,0.f); h2[cg*8+5]=fmaxf(v5,0.f);
                h2[cg*8+6]=fmaxf(v6,0.f); h2[cg*8+7]=fmaxf(v7,0.f);
            }
            bool valid = (j < cnt);
#pragma unroll 1
            for (int cg = 0; cg < 8; cg++) {
                ull a01 = pk2(sBC[cg * 8 + 0], sBC[cg * 8 + 1]);
                ull a23 = pk2(sBC[cg * 8 + 2], sBC[cg * 8 + 3]);
                ull a45 = pk2(sBC[cg * 8 + 4], sBC[cg * 8 + 5]);
                ull a67 = pk2(sBC[cg * 8 + 6], sBC[cg * 8 + 7]);
#pragma unroll
                for (int k = 0; k < 32; k++) {
                    float4 w0 = *reinterpret_cast<const float4*>(&sWC[k * 64 + cg * 8]);
                    float4 w1 = *reinterpret_cast<const float4*>(&sWC[k * 64 + cg * 8 + 4]);
                    ull hh = pk2(h2[k], h2[k]);
                    a01 = fma2_(hh, pk2(w0.x, w0.y), a01);
                    a23 = fma2_(hh, pk2(w0.z, w0.w), a23);
                    a45 = fma2_(hh, pk2(w1.x, w1.y), a45);
                    a67 = fma2_(hh, pk2(w1.z, w1.w), a67);
                }
                float v[8];
                upk2(v[0], v[1], a01); upk2(v[2], v[3], a23);
                upk2(v[4], v[5], a45); upk2(v[6], v[7], a67);
#pragma unroll
                for (int u = 0; u < 8; u++) {
                    float vv = valid ? fmaxf(v[u], 0.f) : -CUDART_INF_F;
#pragma unroll
                    for (int off = 16; off; off >>= 1)
                        vv = fmaxf(vv, __shfl_down_sync(FULLMASK, vv, off));
                    v[u] = vv;
                }
                if (lane == 0) {
                    if (r == 0) {
#pragma unroll
                        for (int u = 0; u < 8; u++) sOut[wl][cg * 8 + u] = v[u];
                    } else {
#pragma unroll
                        for (int u = 0; u < 8; u++)
                            sOut[wl][cg * 8 + u] = fmaxf(sOut[wl][cg * 8 + u], v[u]);
                    }
                }
            }
        }
        __syncwarp();
        for (int c0 = lane; c0 < 64; c0 += 32)
            g_feat1[(size_t)q * 64 + c0] = sOut[wl][c0];
        return;
    }

    // ---- role 3: ball2 (polls fps2 progress) ----
    {
        const int lane = threadIdx.x & 31;
        const int wl = threadIdx.x >> 5;
        const int tq = (bid - NB_FPS - NB_S1) * 16 + wl;  // 0..2047
        const int b = tq & 3;
        const int s = tq >> 2;                            // 0..511
        const int q = (b << 9) | s;

        wait_prog(&g_prog2[b], s + 1);

        const float* P = g_qpos1 + (size_t)b * S1 * 3;
        const float* qq = g_qpos2 + (size_t)q * 3;
        float qx = qq[0], qy = qq[1], qz = qq[2];
        int cnt = 0;
        int* out = g_nidx2 + (size_t)q * Kc;
        for (int base = 0; base < S1 && cnt < Kc; base += 32) {
            int i = base + lane;
            const float* p = P + (size_t)i * 3;
            float dx = p[0] - qx, dy = p[1] - qy, dz = p[2] - qz;
            float d = __fmaf_rn(dz, dz, __fmaf_rn(dy, dy, dx * dx));
            bool in = (d <= 1.0f);
            unsigned m = __ballot_sync(FULLMASK, in);
            int pre = __popc(m & ((1u << lane) - 1u));
            int slot = cnt + pre;
            if (in && slot < Kc) out[slot] = i;
            cnt += __popc(m);
        }
        if (cnt > Kc) cnt = Kc;
        for (int j = cnt + lane; j < Kc; j += 32) out[j] = 0;
        if (lane == 0) g_cnt2[q] = cnt;
    }
}

// ---------------- reset: progress counters are stale across graph replays ----------------
__global__ void reset_kernel()
{
    if (threadIdx.x < Bc) { g_prog1[threadIdx.x] = 0; g_prog2[threadIdx.x] = 0; }
}

// ---------------- dense1: 4 independent FFMA2 chains (8 outputs/pass) ----------------
template <int CIN, int COUT>
__device__ __forceinline__ void dense1(const float* h, const float* sW, const float* sB,
                                       float4* __restrict__ o)
{
    static_assert(COUT % 8 == 0, "COUT must be multiple of 8");
#pragma unroll 1
    for (int cg = 0; cg < COUT / 8; cg++) {
        ull a01 = pk2(sB[cg * 8 + 0], sB[cg * 8 + 1]);
        ull a23 = pk2(sB[cg * 8 + 2], sB[cg * 8 + 3]);
        ull a45 = pk2(sB[cg * 8 + 4], sB[cg * 8 + 5]);
        ull a67 = pk2(sB[cg * 8 + 6], sB[cg * 8 + 7]);
#pragma unroll
        for (int k = 0; k < CIN; k++) {
            float4 w0 = *reinterpret_cast<const float4*>(&sW[k * COUT + cg * 8]);
            float4 w1 = *reinterpret_cast<const float4*>(&sW[k * COUT + cg * 8 + 4]);
            ull hh = pk2(h[k], h[k]);
            a01 = fma2_(hh, pk2(w0.x, w0.y), a01);
            a23 = fma2_(hh, pk2(w0.z, w0.w), a23);
            a45 = fma2_(hh, pk2(w1.x, w1.y), a45);
            a67 = fma2_(hh, pk2(w1.z, w1.w), a67);
        }
        float x0, x1, x2, x3, x4, x5, x6, x7;
        upk2(x0, x1, a01); upk2(x2, x3, a23);
        upk2(x4, x5, a45); upk2(x6, x7, a67);
        o[cg * 2]     = make_float4(fmaxf(x0, 0.f), fmaxf(x1, 0.f), fmaxf(x2, 0.f), fmaxf(x3, 0.f));
        o[cg * 2 + 1] = make_float4(fmaxf(x4, 0.f), fmaxf(x5, 0.f), fmaxf(x6, 0.f), fmaxf(x7, 0.f));
    }
}

// ---------------- Stage2 FUSED layers A+B: gather -> 67->64 -> 64->64 ----------------
// h0 is dead before h1 accumulation, so register peak matches the old layerA2.
// Kills the 33MB bufA round trip + one launch.
__global__ void __launch_bounds__(128)
layerAB2_kernel(const float* __restrict__ feat1, const float* __restrict__ pos1,
                const float* __restrict__ qpos2, const int* __restrict__ nidx,
                const float* __restrict__ Wa, const float* __restrict__ Ba,
                const float* __restrict__ Wb, const float* __restrict__ Bb,
                float* __restrict__ out)
{
    __shared__ __align__(16) float sWa[67 * 64];
    __shared__ float sBa[64];
    __shared__ __align__(16) float sWb[64 * 64];
    __shared__ float sBb[64];
    for (int i = threadIdx.x; i < 67 * 64; i += 128) sWa[i] = Wa[i];
    for (int i = threadIdx.x; i < 64 * 64; i += 128) sWb[i] = Wb[i];
    if (threadIdx.x < 64) { sBa[threadIdx.x] = Ba[threadIdx.x]; sBb[threadIdx.x] = Bb[threadIdx.x]; }
    __syncthreads();

    int t = blockIdx.x * 128 + threadIdx.x;
    int q = t >> 6;
    int b = q >> 9;
    int idx = nidx[t];
    const float* f = feat1 + (size_t)(b * S1 + idx) * 64;
    const float* pp = pos1 + (size_t)(b * S1 + idx) * 3;
    const float* qq = qpos2 + (size_t)q * 3;

    float h0[67];
#pragma unroll
    for (int k = 0; k < 64; k += 4) {
        float4 v = *reinterpret_cast<const float4*>(f + k);
        h0[k] = v.x; h0[k + 1] = v.y; h0[k + 2] = v.z; h0[k + 3] = v.w;
    }
    h0[64] = pp[0] - qq[0]; h0[65] = pp[1] - qq[1]; h0[66] = pp[2] - qq[2];

    float h1[64];
    dense1<67, 64>(h0, sWa, sBa, (float4*)h1);
    dense1<64, 64>(h1, sWb, sBb, (float4*)(out + (size_t)t * 64));
}

// ---------------- Stage2 layer C + masked max-pool (warp/query, 2 nbrs/lane) ----------------
template <int C2, int COUT, int NTH, bool TAIL>
__global__ void __launch_bounds__(NTH)
layerC_kernel(const float* __restrict__ in, const int* __restrict__ cnt,
              const float* __restrict__ W, const float* __restrict__ bias,
              float* __restrict__ out, int totalq,
              const float* __restrict__ qpos2, int mode)
{
    constexpr int NW = NTH / 32;
    if (TAIL && (int)blockIdx.x >= totalq / NW) {
        if (mode) {
            int i = ((int)blockIdx.x - totalq / NW) * NTH + threadIdx.x;
            const int featN = Bc * S2 * 128;
            const int posN = Bc * S2 * 3;
            if (i < posN) out[featN + i] = qpos2[i];
            if (mode >= 2 && i < Bc * S2) out[featN + posN + i] = (float)(i / S2);
        }
        return;
    }
    __shared__ __align__(16) float sW[C2 * COUT];
    __shared__ float sB[COUT];
    for (int i = threadIdx.x; i < C2 * COUT; i += NTH) sW[i] = W[i];
    for (int i = threadIdx.x; i < COUT; i += NTH) sB[i] = bias[i];
    __syncthreads();

    int lane = threadIdx.x & 31;
    int wl = threadIdx.x >> 5;
    int q = blockIdx.x * NW + wl;
    if (q >= totalq) return;
    int c = cnt[q];
    bool va = lane < c, vb = lane + 32 < c;

    float ha[C2], hb[C2];
    const float* fa = in + ((size_t)q * Kc + lane) * C2;
    const float* fb = fa + 32 * C2;
#pragma unroll
    for (int k = 0; k < C2; k += 4) {
        float4 u = *reinterpret_cast<const float4*>(fa + k);
        float4 v = *reinterpret_cast<const float4*>(fb + k);
        ha[k] = u.x; ha[k + 1] = u.y; ha[k + 2] = u.z; ha[k + 3] = u.w;
        hb[k] = v.x; hb[k + 1] = v.y; hb[k + 2] = v.z; hb[k + 3] = v.w;
    }

#pragma unroll 1
    for (int cg = 0; cg < COUT / 4; cg++) {
        ull a01 = pk2(sB[cg * 4 + 0], sB[cg * 4 + 1]);
        ull a23 = pk2(sB[cg * 4 + 2], sB[cg * 4 + 3]);
        ull b01 = a01, b23 = a23;
#pragma unroll
        for (int k = 0; k < C2; k++) {
            float4 w = *reinterpret_cast<const float4*>(&sW[k * COUT + cg * 4]);
            ull w01 = pk2(w.x, w.y), w23 = pk2(w.z, w.w);
            ull hA = pk2(ha[k], ha[k]);
            ull hB = pk2(hb[k], hb[k]);
            a01 = fma2_(hA, w01, a01); a23 = fma2_(hA, w23, a23);
            b01 = fma2_(hB, w01, b01); b23 = fma2_(hB, w23, b23);
        }
        float x0, x1, x2, x3, y0, y1, y2, y3;
        upk2(x0, x1, a01); upk2(x2, x3, a23);
        upk2(y0, y1, b01); upk2(y2, y3, b23);
        x0 = va ? fmaxf(x0, 0.f) : -CUDART_INF_F;
        x1 = va ? fmaxf(x1, 0.f) : -CUDART_INF_F;
        x2 = va ? fmaxf(x2, 0.f) : -CUDART_INF_F;
        x3 = va ? fmaxf(x3, 0.f) : -CUDART_INF_F;
        y0 = vb ? fmaxf(y0, 0.f) : -CUDART_INF_F;
        y1 = vb ? fmaxf(y1, 0.f) : -CUDART_INF_F;
        y2 = vb ? fmaxf(y2, 0.f) : -CUDART_INF_F;
        y3 = vb ? fmaxf(y3, 0.f) : -CUDART_INF_F;
        float v0 = fmaxf(x0, y0), v1 = fmaxf(x1, y1);
        float v2 = fmaxf(x2, y2), v3 = fmaxf(x3, y3);
#pragma unroll
        for (int off = 16; off; off >>= 1) {
            v0 = fmaxf(v0, __shfl_down_sync(FULLMASK, v0, off));
            v1 = fmaxf(v1, __shfl_down_sync(FULLMASK, v1, off));
            v2 = fmaxf(v2, __shfl_down_sync(FULLMASK, v2, off));
            v3 = fmaxf(v3, __shfl_down_sync(FULLMASK, v3, off));
        }
        if (lane == 0)
            *reinterpret_cast<float4*>(out + (size_t)q * COUT + cg * 4) =
                make_float4(v0, v1, v2, v3);
    }
}

extern "C" void kernel_launch(void* const* d_in, const int* in_sizes, int n_in,
                              void* d_out, int out_size)
{
    const float* x   = (const float*)d_in[0];
    const float* w1a = (const float*)d_in[1];  const float* b1a = (const float*)d_in[2];
    const float* w1b = (const float*)d_in[3];  const float* b1b = (const float*)d_in[4];
    const float* w1c = (const float*)d_in[5];  const float* b1c = (const float*)d_in[6];
    const float* w2a = (const float*)d_in[7];  const float* b2a = (const float*)d_in[8];
    const float* w2b = (const float*)d_in[9];  const float* b2b = (const float*)d_in[10];
    const float* w2c = (const float*)d_in[11]; const float* b2c = (const float*)d_in[12];
    float* out = (float*)d_out;

    void *pq1, *pq2, *pn2, *pc2, *pf1, *pb;
    cudaGetSymbolAddress(&pq1, g_qpos1);
    cudaGetSymbolAddress(&pq2, g_qpos2);
    cudaGetSymbolAddress(&pn2, g_nidx2);
    cudaGetSymbolAddress(&pc2, g_cnt2);
    cudaGetSymbolAddress(&pf1, g_feat1);
    cudaGetSymbolAddress(&pb, g_bufB);
    float* qpos1 = (float*)pq1;  float* qpos2 = (float*)pq2;
    int* nidx2 = (int*)pn2;      int* cnt2 = (int*)pc2;
    float* feat1 = (float*)pf1;  float* bufB = (float*)pb;

    const int featN = Bc * S2 * 128;
    const int posN = Bc * S2 * 3;
    int mode = 0;
    if (out_size >= featN + posN) mode = 1;
    if (out_size >= featN + posN + Bc * S2) mode = 2;

    // 120KB dynamic smem: holds fps1's 64KB point cache AND forces occupancy 1
    // (120KB dyn + ~22KB static > 228KB/2), so producer CTAs own their SMs.
    const int MEGA_SMEM = 120 * 1024;
    cudaFuncSetAttribute((const void*)mega_kernel,
                         cudaFuncAttributeMaxDynamicSharedMemorySize, MEGA_SMEM);

    // K0: reset progress counters (stale across graph replays)
    reset_kernel<<<1, 32>>>();

    // K1: mega — fps1+fps2 producers || stage1 per-query pipeline || ball2
    mega_kernel<<<NB_MEGA, NTHM, MEGA_SMEM>>>(x, w1a, b1a, w1b, b1b, w1c, b1c);

    // K2: stage2 fused layers A+B
    layerAB2_kernel<<<(Bc * S2 * Kc) / 128, 128>>>(feat1, qpos1, qpos2, nidx2,
                                                   w2a, b2a, w2b, b2b, bufB);

    // K3: stage2 layer C + maxpool, with tail blocks for optional pos/batch outputs
    {
        int nq = (Bc * S2) / 4;
        int tailBlks = (posN + 127) / 128 + 1;
        layerC_kernel<64, 128, 128, true><<<nq + tailBlks, 128>>>(
            bufB, cnt2, w2c, b2c, out, Bc * S2, qpos2, mode);
    }
}